// round 1
// baseline (speedup 1.0000x reference)
#include <cuda_runtime.h>
#include <math.h>

// Scratch: T_max * 16 floats each. T = 2048 in this problem; padded to 4096.
#define T_MAX 4096
__device__ float g_A[T_MAX * 16];     // per-step A*dt
__device__ float g_S[T_MAX * 16];     // cumsum
__device__ float g_E[T_MAX * 16];     // expm(cumsum)

// ---------------------------------------------------------------------------
// Kernel 1: per-time-step MLP -> A[t] = (MLP(t_avg) + M0) * dt
// One block (128 threads) per time step.
// ---------------------------------------------------------------------------
__global__ void mlp_kernel(const float* __restrict__ t,
                           const float* __restrict__ M0,
                           const float* __restrict__ W1, const float* __restrict__ b1,
                           const float* __restrict__ W2, const float* __restrict__ b2,
                           const float* __restrict__ W3, const float* __restrict__ b3,
                           int T) {
    int i = blockIdx.x;          // time step
    int j = threadIdx.x;         // hidden unit 0..127
    if (i >= T) return;

    __shared__ float h1[128];
    __shared__ float h2[128];

    float tp = (i == 0) ? 0.0f : t[i - 1];
    float tc = t[i];
    float dt = tc - tp;
    float tavg = 0.5f * (tc + tp);

    // layer 1: scalar input
    h1[j] = tanhf(tavg * W1[j] + b1[j]);
    __syncthreads();

    // layer 2: 128 x 128, W2 stored (in, out) row-major -> W2[k*128 + j]
    float s = b2[j];
#pragma unroll 8
    for (int k = 0; k < 128; k++) s += h1[k] * W2[k * 128 + j];
    h2[j] = tanhf(s);
    __syncthreads();

    // layer 3: 128 -> 16, W3[k*16 + p]
    if (j < 16) {
        float a = b3[j];
#pragma unroll 8
        for (int k = 0; k < 128; k++) a += h2[k] * W3[k * 16 + j];
        a += M0[j];
        g_A[i * 16 + j] = a * dt;
    }
}

// ---------------------------------------------------------------------------
// Kernel 2: prefix sum over T for each of the 16 matrix components.
// 16 blocks (one per component) x 128 threads; each thread owns a contiguous
// chunk. Double accumulation for safety.
// ---------------------------------------------------------------------------
__global__ void scan_kernel(int T) {
    int c = blockIdx.x;          // component 0..15
    int tid = threadIdx.x;       // 0..127
    int per = (T + 127) / 128;   // chunk length (16 for T=2048)

    double local[32];            // per >= chunk; T_MAX/128 = 32
    double sum = 0.0;
    int base = tid * per;
    for (int k = 0; k < per; k++) {
        int idx = base + k;
        if (idx < T) sum += (double)g_A[idx * 16 + c];
        local[k] = sum;
    }

    __shared__ double ts[128];
    ts[tid] = sum;
    __syncthreads();

    double off = 0.0;
    for (int k = 0; k < tid; k++) off += ts[k];

    for (int k = 0; k < per; k++) {
        int idx = base + k;
        if (idx < T) g_S[idx * 16 + c] = (float)(off + local[k]);
    }
}

// ---------------------------------------------------------------------------
// Kernel 3: 4x4 matrix exponential per time step (scaling+squaring, Taylor-12).
// One thread per matrix.
// ---------------------------------------------------------------------------
__global__ void expm_kernel(int T) {
    int i = blockIdx.x * blockDim.x + threadIdx.x;
    if (i >= T) return;

    float a[16];
#pragma unroll
    for (int p = 0; p < 16; p++) a[p] = g_S[i * 16 + p];

    // inf-norm
    float nrm = 0.0f;
#pragma unroll
    for (int r = 0; r < 4; r++) {
        float rs = 0.0f;
#pragma unroll
        for (int c = 0; c < 4; c++) rs += fabsf(a[r * 4 + c]);
        nrm = fmaxf(nrm, rs);
    }
    int s = 0;
    while (nrm > 0.5f && s < 40) { nrm *= 0.5f; s++; }
    float sc = ldexpf(1.0f, -s);
#pragma unroll
    for (int p = 0; p < 16; p++) a[p] *= sc;

    // Taylor series: E = I + A + A^2/2! + ... + A^12/12!
    float P[16], E[16];
#pragma unroll
    for (int p = 0; p < 16; p++) { P[p] = a[p]; E[p] = a[p]; }
#pragma unroll
    for (int d = 0; d < 4; d++) E[d * 5] += 1.0f;

    for (int k = 2; k <= 12; k++) {
        float Q[16];
        float inv = 1.0f / (float)k;
#pragma unroll
        for (int r = 0; r < 4; r++)
#pragma unroll
            for (int c = 0; c < 4; c++) {
                float v = 0.0f;
#pragma unroll
                for (int m = 0; m < 4; m++) v += P[r * 4 + m] * a[m * 4 + c];
                Q[r * 4 + c] = v * inv;
            }
#pragma unroll
        for (int p = 0; p < 16; p++) { P[p] = Q[p]; E[p] += Q[p]; }
    }

    // repeated squaring
    for (int q = 0; q < s; q++) {
        float Q[16];
#pragma unroll
        for (int r = 0; r < 4; r++)
#pragma unroll
            for (int c = 0; c < 4; c++) {
                float v = 0.0f;
#pragma unroll
                for (int m = 0; m < 4; m++) v += E[r * 4 + m] * E[m * 4 + c];
                Q[r * 4 + c] = v;
            }
#pragma unroll
        for (int p = 0; p < 16; p++) E[p] = Q[p];
    }

#pragma unroll
    for (int p = 0; p < 16; p++) g_E[i * 16 + p] = E[p];
}

// ---------------------------------------------------------------------------
// Kernel 4 (the heavy one): out[t,n,:] = E[t] @ x[n,:]
// 256 MB of f32 stores -> pure HBM-store-bound. Tile TT=8 time steps per
// block so each thread's float4 x-load amortizes over 8 coalesced float4
// stores.
// ---------------------------------------------------------------------------
#define TT 8
__global__ void apply_kernel(const float* __restrict__ x,
                             float4* __restrict__ out,
                             int N, int T) {
    int tbase = blockIdx.y * TT;
    int n = blockIdx.x * blockDim.x + threadIdx.x;

    __shared__ float Es[TT * 16];
    int nt = T - tbase; if (nt > TT) nt = TT;
    if (threadIdx.x < nt * 16) Es[threadIdx.x] = g_E[tbase * 16 + threadIdx.x];
    __syncthreads();

    if (n >= N) return;
    float4 xv = ((const float4*)x)[n];

#pragma unroll
    for (int k = 0; k < TT; k++) {
        if (k >= nt) break;
        const float* e = &Es[k * 16];
        float4 o;
        o.x = e[0]  * xv.x + e[1]  * xv.y + e[2]  * xv.z + e[3]  * xv.w;
        o.y = e[4]  * xv.x + e[5]  * xv.y + e[6]  * xv.z + e[7]  * xv.w;
        o.z = e[8]  * xv.x + e[9]  * xv.y + e[10] * xv.z + e[11] * xv.w;
        o.w = e[12] * xv.x + e[13] * xv.y + e[14] * xv.z + e[15] * xv.w;
        out[(size_t)(tbase + k) * N + n] = o;
    }
}

// ---------------------------------------------------------------------------
extern "C" void kernel_launch(void* const* d_in, const int* in_sizes, int n_in,
                              void* d_out, int out_size) {
    const float* x  = (const float*)d_in[0];   // (N, 4)
    const float* t  = (const float*)d_in[1];   // (T,)
    const float* M0 = (const float*)d_in[2];   // (4,4)
    const float* W1 = (const float*)d_in[3];   // (1,128)
    const float* b1 = (const float*)d_in[4];   // (128,)
    const float* W2 = (const float*)d_in[5];   // (128,128)
    const float* b2 = (const float*)d_in[6];   // (128,)
    const float* W3 = (const float*)d_in[7];   // (128,16)
    const float* b3 = (const float*)d_in[8];   // (16,)
    float* out = (float*)d_out;

    int N = in_sizes[0] / 4;
    int T = in_sizes[1];

    mlp_kernel<<<T, 128>>>(t, M0, W1, b1, W2, b2, W3, b3, T);
    scan_kernel<<<16, 128>>>(T);
    expm_kernel<<<(T + 127) / 128, 128>>>(T);

    dim3 grid((N + 255) / 256, (T + TT - 1) / TT);
    apply_kernel<<<grid, 256>>>(x, (float4*)out, N, T);
}